// round 1
// baseline (speedup 1.0000x reference)
#include <cuda_runtime.h>
#include <math.h>

// Problem dims
#define Bd   8
#define Nd   1000
#define Ed   4
#define Dd   64
#define ADd  32
#define NEd  4000        // N*E
#define BNT  8000        // B*N

// GEMM tiling
#define BM 64
#define BN 64
#define BK 32

// ---------------- device scratch (no allocations allowed) ----------------
__device__ float g_WT[8 * 64 * 64];        // (dir*4+e, d, f): W[e][f][d] transposed
__device__ float g_WrzT[192 * 128];        // [k][c]: c<64 -> W_r[c][k], else W_z[c-64][k]
__device__ float g_WhT[192 * 64];          // [k][d] = W_h[d][k]
__device__ float g_Wo1T[96 * 64];          // [k][d] = Wo1[d][k]
__device__ float g_SP[16L * NEd * Dd];     // (b*2+dir) x 4000 x 64
__device__ float g_abuf[(long)BNT * 192];  // [a_in | a_out | state or r*state]
__device__ float g_rz[(long)BNT * 128];    // r_pre | z_pre
__device__ float g_hb[(long)BNT * 64];     // h_pre
__device__ float g_s1[(long)BNT * 64];
__device__ float g_s2[(long)BNT * 64];

__device__ __forceinline__ const float* sel_state(int sel, const float* prop) {
    return sel == 0 ? prop : (sel == 1 ? (const float*)g_s1 : (const float*)g_s2);
}

// ---------------- generic 64x64 fp32 GEMM tile (double-buffered) ----------------
// C[m][n] = sum_k A[m][k] * B[k][n], for one 64x64 tile; K % 32 == 0; 64 cols always full.
__device__ __forceinline__ void gemm_tile(
    const float* __restrict__ A, long lda,
    const float* __restrict__ Bm, int ldb,
    float* __restrict__ C, int ldc,
    int rowsValid, int K)
{
    __shared__ float As[2][BM][BK + 4];   // [m][k], padded
    __shared__ float Bs[2][BK][BN];       // [k][n]

    const int tid = threadIdx.x;
    const int tx = tid & 15;
    const int ty = tid >> 4;

    float acc[4][4];
#pragma unroll
    for (int i = 0; i < 4; i++)
#pragma unroll
        for (int j = 0; j < 4; j++) acc[i][j] = 0.f;

    const int am0 = tid >> 3;    // 0..31  (A row slot; +32 for second)
    const int akv = tid & 7;     // which float4 along k
    const int bk0 = tid >> 4;    // 0..15  (B row slot; +16 for second)
    const int bnv = tid & 15;    // which float4 along n

    const int nk = K / BK;

    // prologue: load tile 0 into buffer 0
#pragma unroll
    for (int s = 0; s < 2; s++) {
        int m = am0 + s * 32;
        float4 v = make_float4(0.f, 0.f, 0.f, 0.f);
        if (m < rowsValid) v = *(const float4*)(A + (long)m * lda + akv * 4);
        *(float4*)&As[0][m][akv * 4] = v;
        int kk = bk0 + s * 16;
        float4 w = *(const float4*)(Bm + (long)kk * ldb + bnv * 4);
        *(float4*)&Bs[0][kk][bnv * 4] = w;
    }
    __syncthreads();

    for (int kt = 0; kt < nk; ++kt) {
        int cur = kt & 1, nxt = cur ^ 1;
        if (kt + 1 < nk) {
#pragma unroll
            for (int s = 0; s < 2; s++) {
                int m = am0 + s * 32;
                float4 v = make_float4(0.f, 0.f, 0.f, 0.f);
                if (m < rowsValid)
                    v = *(const float4*)(A + (long)m * lda + (long)(kt + 1) * BK + akv * 4);
                *(float4*)&As[nxt][m][akv * 4] = v;
                int kk = bk0 + s * 16;
                float4 w = *(const float4*)(Bm + (long)((kt + 1) * BK + kk) * ldb + bnv * 4);
                *(float4*)&Bs[nxt][kk][bnv * 4] = w;
            }
        }
#pragma unroll
        for (int k = 0; k < BK; k++) {
            float a0 = As[cur][4 * ty + 0][k];
            float a1 = As[cur][4 * ty + 1][k];
            float a2 = As[cur][4 * ty + 2][k];
            float a3 = As[cur][4 * ty + 3][k];
            float4 b = *(float4*)&Bs[cur][k][4 * tx];
            acc[0][0] += a0 * b.x; acc[0][1] += a0 * b.y; acc[0][2] += a0 * b.z; acc[0][3] += a0 * b.w;
            acc[1][0] += a1 * b.x; acc[1][1] += a1 * b.y; acc[1][2] += a1 * b.z; acc[1][3] += a1 * b.w;
            acc[2][0] += a2 * b.x; acc[2][1] += a2 * b.y; acc[2][2] += a2 * b.z; acc[2][3] += a2 * b.w;
            acc[3][0] += a3 * b.x; acc[3][1] += a3 * b.y; acc[3][2] += a3 * b.z; acc[3][3] += a3 * b.w;
        }
        __syncthreads();
    }

#pragma unroll
    for (int i = 0; i < 4; i++) {
        int m = 4 * ty + i;
        if (m < rowsValid) {
            float4 o = make_float4(acc[i][0], acc[i][1], acc[i][2], acc[i][3]);
            *(float4*)(C + (long)m * ldc + 4 * tx) = o;
        }
    }
}

// ---------------- GEMM wrappers ----------------

// sproj: SP[(b,dir)][e*N+n][f] = sum_d state[b][n][d] * W[e][f][d]
// grid: x=16 row tiles, z=64: z = ((b*2+dir)*4 + e)
__global__ void __launch_bounds__(256) k_sproj(const float* __restrict__ prop, int sel) {
    const float* state = sel_state(sel, prop);
    int z = blockIdx.z;
    int e = z & 3;
    int bd = z >> 2;
    int dir = bd & 1;
    int b = bd >> 1;
    int r0 = blockIdx.x * BM;
    int rowsValid = min(BM, Nd - r0);
    const float* A = state + (long)b * Nd * Dd + (long)r0 * Dd;
    const float* Bm = g_WT + (dir * 4 + e) * 64 * 64;
    float* C = g_SP + ((long)(b * 2 + dir) * NEd + (long)e * Nd + r0) * Dd;
    gemm_tile(A, Dd, Bm, 64, C, 64, rowsValid, 64);
}

// big: abuf[b*N+i][dir*64 + f] = sum_j A[b][i][dir*4000 + j] * SP[(b,dir)][j][f]
// grid: x=16 row tiles, z=16: z = b*2+dir
__global__ void __launch_bounds__(256) k_big(const float* __restrict__ Aall) {
    int z = blockIdx.z;
    int dir = z & 1;
    int b = z >> 1;
    int r0 = blockIdx.x * BM;
    int rowsValid = min(BM, Nd - r0);
    const float* A = Aall + (long)b * Nd * (2 * NEd) + (long)r0 * (2 * NEd) + (long)dir * NEd;
    const float* Bm = g_SP + (long)(b * 2 + dir) * NEd * Dd;
    float* C = g_abuf + ((long)b * Nd + r0) * 192 + dir * 64;
    gemm_tile(A, 2 * NEd, Bm, 64, C, 192, rowsValid, NEd);
}

// rz: g_rz = abuf(8000x192) @ WrzT(192x128). grid: x=125, y=2
__global__ void __launch_bounds__(256) k_rz() {
    int r0 = blockIdx.x * BM;
    int c0 = blockIdx.y * BN;
    gemm_tile(g_abuf + (long)r0 * 192, 192, g_WrzT + c0, 128,
              g_rz + (long)r0 * 128 + c0, 128, BM, 192);
}

// h: g_hb = abuf(8000x192) @ WhT(192x64). grid: x=125
__global__ void __launch_bounds__(256) k_h() {
    int r0 = blockIdx.x * BM;
    gemm_tile(g_abuf + (long)r0 * 192, 192, g_WhT, 64,
              g_hb + (long)r0 * 64, 64, BM, 192);
}

// ---------------- elementwise kernels ----------------

__global__ void k_pack_weights(const float* __restrict__ W_in, const float* __restrict__ W_out,
                               const float* __restrict__ W_r, const float* __restrict__ W_z,
                               const float* __restrict__ W_h, const float* __restrict__ Wo1) {
    int idx = blockIdx.x * blockDim.x + threadIdx.x;
    if (idx < 32768) {
        int g = idx >> 12;          // dir*4+e
        int r = idx & 4095;
        int d = r >> 6;             // contraction dim
        int f = r & 63;             // output feature
        int e = g & 3;
        const float* W = (g < 4) ? W_in : W_out;
        g_WT[idx] = W[e * 4096 + f * 64 + d];
    } else if (idx < 57344) {
        int j = idx - 32768;
        int k = j >> 7;
        int c = j & 127;
        g_WrzT[j] = (c < 64) ? W_r[c * 192 + k] : W_z[(c - 64) * 192 + k];
    } else if (idx < 69632) {
        int j = idx - 57344;
        int k = j >> 6;
        int d = j & 63;
        g_WhT[j] = W_h[d * 192 + k];
    } else if (idx < 75776) {
        int j = idx - 69632;
        int k = j >> 6;
        int d = j & 63;
        g_Wo1T[j] = Wo1[d * 96 + k];
    }
}

// abuf[:,128:192] = state
__global__ void k_pack_state(const float* __restrict__ prop, int sel) {
    const float* s = sel_state(sel, prop);
    int idx = blockIdx.x * blockDim.x + threadIdx.x;
    if (idx < BNT * 64) {
        int bn = idx >> 6;
        int d = idx & 63;
        g_abuf[(long)bn * 192 + 128 + d] = s[idx];
    }
}

// abuf[:,128:192] = sigmoid(r_pre) * state
__global__ void k_gates_r(const float* __restrict__ prop, int sel) {
    const float* s = sel_state(sel, prop);
    int idx = blockIdx.x * blockDim.x + threadIdx.x;
    if (idx < BNT * 64) {
        int bn = idx >> 6;
        int d = idx & 63;
        float r = 1.f / (1.f + expf(-g_rz[(long)bn * 128 + d]));
        g_abuf[(long)bn * 192 + 128 + d] = r * s[idx];
    }
}

// s_out = (1-z)*s + z*tanh(h_pre)
__global__ void k_update(const float* __restrict__ prop, int sel_in, int sel_out) {
    const float* s = sel_state(sel_in, prop);
    float* so = (sel_out == 1) ? g_s1 : g_s2;
    int idx = blockIdx.x * blockDim.x + threadIdx.x;
    if (idx < BNT * 64) {
        int bn = idx >> 6;
        int d = idx & 63;
        float z = 1.f / (1.f + expf(-g_rz[(long)bn * 128 + 64 + d]));
        float h = tanhf(g_hb[idx]);
        so[idx] = (1.f - z) * s[idx] + z * h;
    }
}

// out[bn] = sum_d tanh( sum_k join[bn][k] * Wo1[d][k] ) * Wo2[d],  join = [s2 | annotation]
// grid: 250 blocks x 256 threads; 32 rows per block
__global__ void __launch_bounds__(256) k_out(const float* __restrict__ ann,
                                             const float* __restrict__ Wo2,
                                             float* __restrict__ out) {
    __shared__ float Wo1s[96 * 64];
    __shared__ float Wo2s[64];
    __shared__ float joins[32][96];
    __shared__ float part[8];

    int tid = threadIdx.x;
    for (int i = tid; i < 96 * 64; i += 256) Wo1s[i] = g_Wo1T[i];
    if (tid < 64) Wo2s[tid] = Wo2[tid];

    int base = blockIdx.x * 32;
    for (int i = tid; i < 32 * 96; i += 256) {
        int rr = i / 96;
        int k = i - rr * 96;
        int bn = base + rr;
        joins[rr][k] = (k < 64) ? g_s2[(long)bn * 64 + k] : ann[(long)bn * 32 + (k - 64)];
    }
    __syncthreads();

    int q = tid >> 6;     // 0..3 (row within group of 4)
    int d = tid & 63;     // output feature
    for (int rr = 0; rr < 32; rr += 4) {
        int r = rr + q;
        float acc = 0.f;
#pragma unroll
        for (int k = 0; k < 96; k++) acc += joins[r][k] * Wo1s[k * 64 + d];
        float v = tanhf(acc) * Wo2s[d];
#pragma unroll
        for (int off = 16; off > 0; off >>= 1)
            v += __shfl_down_sync(0xffffffffu, v, off);
        int w = tid >> 5;
        if ((tid & 31) == 0) part[w] = v;
        __syncthreads();
        if (tid < 4) out[base + rr + tid] = part[2 * tid] + part[2 * tid + 1];
        __syncthreads();
    }
}

// ---------------- launch ----------------
extern "C" void kernel_launch(void* const* d_in, const int* in_sizes, int n_in,
                              void* d_out, int out_size) {
    const float* prop  = (const float*)d_in[0];
    const float* ann   = (const float*)d_in[1];
    const float* A     = (const float*)d_in[2];
    const float* W_in  = (const float*)d_in[3];
    const float* W_out = (const float*)d_in[4];
    const float* W_r   = (const float*)d_in[5];
    const float* W_z   = (const float*)d_in[6];
    const float* W_h   = (const float*)d_in[7];
    const float* Wo1   = (const float*)d_in[8];
    const float* Wo2   = (const float*)d_in[9];
    float* out = (float*)d_out;

    const int EW_BLOCKS = (BNT * 64 + 255) / 256;

    k_pack_weights<<<(75776 + 255) / 256, 256>>>(W_in, W_out, W_r, W_z, W_h, Wo1);

    // ---- propagate step 1 (state = prop_state, sel=0 -> out g_s1) ----
    k_pack_state<<<EW_BLOCKS, 256>>>(prop, 0);
    k_sproj<<<dim3(16, 1, 64), 256>>>(prop, 0);
    k_big<<<dim3(16, 1, 16), 256>>>(A);
    k_rz<<<dim3(125, 2, 1), 256>>>();
    k_gates_r<<<EW_BLOCKS, 256>>>(prop, 0);
    k_h<<<dim3(125, 1, 1), 256>>>();
    k_update<<<EW_BLOCKS, 256>>>(prop, 0, 1);

    // ---- propagate step 2 (state = g_s1, sel=1 -> out g_s2) ----
    k_pack_state<<<EW_BLOCKS, 256>>>(prop, 1);
    k_sproj<<<dim3(16, 1, 64), 256>>>(prop, 1);
    k_big<<<dim3(16, 1, 16), 256>>>(A);
    k_rz<<<dim3(125, 2, 1), 256>>>();
    k_gates_r<<<EW_BLOCKS, 256>>>(prop, 1);
    k_h<<<dim3(125, 1, 1), 256>>>();
    k_update<<<EW_BLOCKS, 256>>>(prop, 1, 2);

    // ---- output head ----
    k_out<<<250, 256>>>(ann, Wo2, out);
}

// round 3
// speedup vs baseline: 1.9949x; 1.9949x over previous
#include <cuda_runtime.h>
#include <math.h>
#include <stdint.h>

// Problem dims
#define Bd   8
#define Nd   1000
#define Ed   4
#define Dd   64
#define ADd  32
#define NEd  4000        // N*E
#define BNT  8000        // B*N

// SIMT GEMM tiling (small GEMMs)
#define BM 64
#define BN 64
#define BK 32

// mma big-GEMM config
#define KC 32                         // K chunk (tf32 elems)
#define NK (NEd / KC)                 // 125
#define AST 36                        // padded row stride (floats)
#define A_STAGE (128 * AST)           // 4608 floats
#define B_STAGE (64 * AST)            // 2304 floats
#define STAGE_FLOATS (A_STAGE + B_STAGE)   // 6912
#define SMEM_DYN (2 * STAGE_FLOATS * 4)    // 55296 bytes

// ---------------- device scratch ----------------
__device__ __align__(16) float g_WT[8 * 64 * 64];
__device__ __align__(16) float g_WrzT[192 * 128];
__device__ __align__(16) float g_WhT[192 * 64];
__device__ __align__(16) float g_Wo1T[96 * 64];
__device__ __align__(16) float g_SPT[16L * 64 * NEd];   // (b*2+dir) x 64(f) x 4000(j), tf32-rounded
__device__ __align__(16) float g_abuf[(long)BNT * 192];
__device__ __align__(16) float g_rz[(long)BNT * 128];
__device__ __align__(16) float g_hb[(long)BNT * 64];
__device__ __align__(16) float g_s1[(long)BNT * 64];
__device__ __align__(16) float g_s2[(long)BNT * 64];

__device__ __forceinline__ const float* sel_state(int sel, const float* prop) {
    return sel == 0 ? prop : (sel == 1 ? (const float*)g_s1 : (const float*)g_s2);
}

__device__ __forceinline__ float to_tf32(float x) {
    float r; asm("cvt.rna.tf32.f32 %0, %1;" : "=f"(r) : "f"(x)); return r;
}

__device__ __forceinline__ void mma16n8k8(float* c, const uint32_t* a, const uint32_t* b) {
    asm volatile(
        "mma.sync.aligned.m16n8k8.row.col.f32.tf32.tf32.f32 "
        "{%0,%1,%2,%3}, {%4,%5,%6,%7}, {%8,%9}, {%0,%1,%2,%3};"
        : "+f"(c[0]), "+f"(c[1]), "+f"(c[2]), "+f"(c[3])
        : "r"(a[0]), "r"(a[1]), "r"(a[2]), "r"(a[3]), "r"(b[0]), "r"(b[1]));
}

// ---------------- generic 64x64 fp32 SIMT GEMM tile ----------------
// TRANS_TF32=false: C[m][n], float4 stores.  true: C[n*ldc + m] = tf32(acc) (transposed).
template <bool TRANS_TF32>
__device__ __forceinline__ void gemm_tile(
    const float* __restrict__ A, long lda,
    const float* __restrict__ Bm, int ldb,
    float* __restrict__ C, int ldc,
    int rowsValid, int K)
{
    __shared__ float As[2][BM][BK + 4];
    __shared__ float Bs[2][BK][BN];

    const int tid = threadIdx.x;
    const int tx = tid & 15;
    const int ty = tid >> 4;

    float acc[4][4];
#pragma unroll
    for (int i = 0; i < 4; i++)
#pragma unroll
        for (int j = 0; j < 4; j++) acc[i][j] = 0.f;

    const int am0 = tid >> 3;
    const int akv = tid & 7;
    const int bk0 = tid >> 4;
    const int bnv = tid & 15;
    const int nk = K / BK;

#pragma unroll
    for (int s = 0; s < 2; s++) {
        int m = am0 + s * 32;
        float4 v = make_float4(0.f, 0.f, 0.f, 0.f);
        if (m < rowsValid) v = *(const float4*)(A + (long)m * lda + akv * 4);
        *(float4*)&As[0][m][akv * 4] = v;
        int kk = bk0 + s * 16;
        float4 w = *(const float4*)(Bm + (long)kk * ldb + bnv * 4);
        *(float4*)&Bs[0][kk][bnv * 4] = w;
    }
    __syncthreads();

    for (int kt = 0; kt < nk; ++kt) {
        int cur = kt & 1, nxt = cur ^ 1;
        if (kt + 1 < nk) {
#pragma unroll
            for (int s = 0; s < 2; s++) {
                int m = am0 + s * 32;
                float4 v = make_float4(0.f, 0.f, 0.f, 0.f);
                if (m < rowsValid)
                    v = *(const float4*)(A + (long)m * lda + (long)(kt + 1) * BK + akv * 4);
                *(float4*)&As[nxt][m][akv * 4] = v;
                int kk = bk0 + s * 16;
                float4 w = *(const float4*)(Bm + (long)((kt + 1) * BK + kk) * ldb + bnv * 4);
                *(float4*)&Bs[nxt][kk][bnv * 4] = w;
            }
        }
#pragma unroll
        for (int k = 0; k < BK; k++) {
            float a0 = As[cur][4 * ty + 0][k];
            float a1 = As[cur][4 * ty + 1][k];
            float a2 = As[cur][4 * ty + 2][k];
            float a3 = As[cur][4 * ty + 3][k];
            float4 b = *(float4*)&Bs[cur][k][4 * tx];
            acc[0][0] += a0 * b.x; acc[0][1] += a0 * b.y; acc[0][2] += a0 * b.z; acc[0][3] += a0 * b.w;
            acc[1][0] += a1 * b.x; acc[1][1] += a1 * b.y; acc[1][2] += a1 * b.z; acc[1][3] += a1 * b.w;
            acc[2][0] += a2 * b.x; acc[2][1] += a2 * b.y; acc[2][2] += a2 * b.z; acc[2][3] += a2 * b.w;
            acc[3][0] += a3 * b.x; acc[3][1] += a3 * b.y; acc[3][2] += a3 * b.z; acc[3][3] += a3 * b.w;
        }
        __syncthreads();
    }

    if (TRANS_TF32) {
#pragma unroll
        for (int i = 0; i < 4; i++) {
            int m = 4 * ty + i;
            if (m < rowsValid) {
#pragma unroll
                for (int j = 0; j < 4; j++)
                    C[(long)(4 * tx + j) * ldc + m] = to_tf32(acc[i][j]);
            }
        }
    } else {
#pragma unroll
        for (int i = 0; i < 4; i++) {
            int m = 4 * ty + i;
            if (m < rowsValid) {
                float4 o = make_float4(acc[i][0], acc[i][1], acc[i][2], acc[i][3]);
                *(float4*)(C + (long)m * ldc + 4 * tx) = o;
            }
        }
    }
}

// ---------------- GEMM wrappers ----------------

// sproj (transposed out): SPT[(bd)][f][e*1000 + n] = tf32( sum_d state[b][n][d] * W[e][f][d] )
__global__ void __launch_bounds__(256) k_sproj(const float* __restrict__ prop, int sel) {
    const float* state = sel_state(sel, prop);
    int z = blockIdx.z;
    int e = z & 3;
    int bd = z >> 2;
    int dir = bd & 1;
    int b = bd >> 1;
    int r0 = blockIdx.x * BM;
    int rowsValid = min(BM, Nd - r0);
    const float* A = state + (long)b * Nd * Dd + (long)r0 * Dd;
    const float* Bm = g_WT + (dir * 4 + e) * 64 * 64;
    float* C = g_SPT + (long)bd * 64 * NEd + (long)e * Nd + r0;
    gemm_tile<true>(A, Dd, Bm, 64, C, NEd, rowsValid, 64);
}

// ---------------- k_big: tf32 mma.sync (tensor pipe via baseline PTX) ----------------
// abuf[b*N + i][dir*64 + f] = sum_j A[b][i][dir*4000+j] * SPT[bd][f][j]
// grid: x=8 (M tiles of 128), y=16 (bd). 256 threads = 8 warps (4x2 of 32x32).
__global__ void __launch_bounds__(256, 1) k_big_mma(const float* __restrict__ Aall) {
    extern __shared__ float dsm[];
    const int tid = threadIdx.x;
    const int wid = tid >> 5, lane = tid & 31;
    const int bd = blockIdx.y, dir = bd & 1, b = bd >> 1;
    const int r0 = blockIdx.x * 128;
    const int rowsValid = min(128, Nd - r0);

    // loader geometry
    const int c4 = tid & 7;     // float4 index along K (0..7)
    const int rr = tid >> 3;    // row slot (0..31)
    const float* baseA = Aall + ((long)b * Nd + r0 + rr) * (2L * NEd)
                              + (long)dir * NEd + c4 * 4;
    const float* baseB = g_SPT + (long)bd * 64 * NEd + (long)rr * NEd + c4 * 4;

    bool apred[4];
#pragma unroll
    for (int j = 0; j < 4; j++) apred[j] = (rr + 32 * j) < rowsValid;

    const float4 z4 = make_float4(0.f, 0.f, 0.f, 0.f);
    float4 cA[4], cB[2];
#pragma unroll
    for (int j = 0; j < 4; j++)
        cA[j] = apred[j] ? *(const float4*)(baseA + (long)(32 * j) * (2L * NEd)) : z4;
#pragma unroll
    for (int j = 0; j < 2; j++)
        cB[j] = *(const float4*)(baseB + (long)(32 * j) * NEd);

    // warp tile position
    const int wm = wid & 3;       // m block (32 rows)
    const int wn = wid >> 2;      // n block (32 cols)
    const int g  = lane >> 2;     // group id 0..7
    const int tg = lane & 3;      // thread-in-group 0..3

    float acc[2][4][4];
#pragma unroll
    for (int mt = 0; mt < 2; mt++)
#pragma unroll
        for (int nt = 0; nt < 4; nt++)
#pragma unroll
            for (int i = 0; i < 4; i++) acc[mt][nt][i] = 0.f;

    for (int kt = 0; kt < NK; kt++) {
        float* As = dsm + (kt & 1) * STAGE_FLOATS;
        float* Bs = As + A_STAGE;

        // STS (A converted to tf32; B already tf32-rounded)
#pragma unroll
        for (int j = 0; j < 4; j++) {
            float4 v = make_float4(to_tf32(cA[j].x), to_tf32(cA[j].y),
                                   to_tf32(cA[j].z), to_tf32(cA[j].w));
            *(float4*)(As + (rr + 32 * j) * AST + c4 * 4) = v;
        }
#pragma unroll
        for (int j = 0; j < 2; j++)
            *(float4*)(Bs + (rr + 32 * j) * AST + c4 * 4) = cB[j];

        // prefetch next chunk into registers (in flight during compute)
        if (kt + 1 < NK) {
#pragma unroll
            for (int j = 0; j < 4; j++)
                cA[j] = apred[j]
                    ? *(const float4*)(baseA + (long)(32 * j) * (2L * NEd) + (kt + 1) * KC)
                    : z4;
#pragma unroll
            for (int j = 0; j < 2; j++)
                cB[j] = *(const float4*)(baseB + (long)(32 * j) * NEd + (kt + 1) * KC);
        }
        __syncthreads();

        const uint32_t* Asu = (const uint32_t*)As;
        const uint32_t* Bsu = (const uint32_t*)Bs;
#pragma unroll
        for (int ks = 0; ks < 4; ks++) {
            const int k8 = ks * 8;
            uint32_t af[2][4];
#pragma unroll
            for (int mt = 0; mt < 2; mt++) {
                int mrow = wm * 32 + mt * 16 + g;
                af[mt][0] = Asu[mrow * AST + k8 + tg];
                af[mt][1] = Asu[(mrow + 8) * AST + k8 + tg];
                af[mt][2] = Asu[mrow * AST + k8 + tg + 4];
                af[mt][3] = Asu[(mrow + 8) * AST + k8 + tg + 4];
            }
            uint32_t bf[4][2];
#pragma unroll
            for (int nt = 0; nt < 4; nt++) {
                int nrow = wn * 32 + nt * 8 + g;
                bf[nt][0] = Bsu[nrow * AST + k8 + tg];
                bf[nt][1] = Bsu[nrow * AST + k8 + tg + 4];
            }
#pragma unroll
            for (int mt = 0; mt < 2; mt++)
#pragma unroll
                for (int nt = 0; nt < 4; nt++)
                    mma16n8k8(acc[mt][nt], af[mt], bf[nt]);
        }
        __syncthreads();
    }

    // epilogue: acc -> g_abuf
#pragma unroll
    for (int mt = 0; mt < 2; mt++) {
        int rl0 = wm * 32 + mt * 16 + g;       // local row for c0/c1
        int rl1 = rl0 + 8;                     // local row for c2/c3
#pragma unroll
        for (int nt = 0; nt < 4; nt++) {
            int col = dir * 64 + wn * 32 + nt * 8 + 2 * tg;
            if (rl0 < rowsValid) {
                float2 v = make_float2(acc[mt][nt][0], acc[mt][nt][1]);
                *(float2*)(g_abuf + ((long)b * Nd + r0 + rl0) * 192 + col) = v;
            }
            if (rl1 < rowsValid) {
                float2 v = make_float2(acc[mt][nt][2], acc[mt][nt][3]);
                *(float2*)(g_abuf + ((long)b * Nd + r0 + rl1) * 192 + col) = v;
            }
        }
    }
}

// rz: g_rz = abuf(8000x192) @ WrzT(192x128)
__global__ void __launch_bounds__(256) k_rz() {
    int r0 = blockIdx.x * BM;
    int c0 = blockIdx.y * BN;
    gemm_tile<false>(g_abuf + (long)r0 * 192, 192, g_WrzT + c0, 128,
                     g_rz + (long)r0 * 128 + c0, 128, BM, 192);
}

// h: g_hb = abuf(8000x192) @ WhT(192x64)
__global__ void __launch_bounds__(256) k_h() {
    int r0 = blockIdx.x * BM;
    gemm_tile<false>(g_abuf + (long)r0 * 192, 192, g_WhT, 64,
                     g_hb + (long)r0 * 64, 64, BM, 192);
}

// ---------------- elementwise kernels ----------------

__global__ void k_pack_weights(const float* __restrict__ W_in, const float* __restrict__ W_out,
                               const float* __restrict__ W_r, const float* __restrict__ W_z,
                               const float* __restrict__ W_h, const float* __restrict__ Wo1) {
    int idx = blockIdx.x * blockDim.x + threadIdx.x;
    if (idx < 32768) {
        int g = idx >> 12;
        int r = idx & 4095;
        int d = r >> 6;
        int f = r & 63;
        int e = g & 3;
        const float* W = (g < 4) ? W_in : W_out;
        g_WT[idx] = W[e * 4096 + f * 64 + d];
    } else if (idx < 57344) {
        int j = idx - 32768;
        int k = j >> 7;
        int c = j & 127;
        g_WrzT[j] = (c < 64) ? W_r[c * 192 + k] : W_z[(c - 64) * 192 + k];
    } else if (idx < 69632) {
        int j = idx - 57344;
        int k = j >> 6;
        int d = j & 63;
        g_WhT[j] = W_h[d * 192 + k];
    } else if (idx < 75776) {
        int j = idx - 69632;
        int k = j >> 6;
        int d = j & 63;
        g_Wo1T[j] = Wo1[d * 96 + k];
    }
}

__global__ void k_pack_state(const float* __restrict__ prop, int sel) {
    const float* s = sel_state(sel, prop);
    int idx = blockIdx.x * blockDim.x + threadIdx.x;
    if (idx < BNT * 64) {
        int bn = idx >> 6;
        int d = idx & 63;
        g_abuf[(long)bn * 192 + 128 + d] = s[idx];
    }
}

__global__ void k_gates_r(const float* __restrict__ prop, int sel) {
    const float* s = sel_state(sel, prop);
    int idx = blockIdx.x * blockDim.x + threadIdx.x;
    if (idx < BNT * 64) {
        int bn = idx >> 6;
        int d = idx & 63;
        float r = 1.f / (1.f + expf(-g_rz[(long)bn * 128 + d]));
        g_abuf[(long)bn * 192 + 128 + d] = r * s[idx];
    }
}

__global__ void k_update(const float* __restrict__ prop, int sel_in, int sel_out) {
    const float* s = sel_state(sel_in, prop);
    float* so = (sel_out == 1) ? g_s1 : g_s2;
    int idx = blockIdx.x * blockDim.x + threadIdx.x;
    if (idx < BNT * 64) {
        int bn = idx >> 6;
        int d = idx & 63;
        float z = 1.f / (1.f + expf(-g_rz[(long)bn * 128 + 64 + d]));
        float h = tanhf(g_hb[idx]);
        so[idx] = (1.f - z) * s[idx] + z * h;
    }
}

__global__ void __launch_bounds__(256) k_out(const float* __restrict__ ann,
                                             const float* __restrict__ Wo2,
                                             float* __restrict__ out) {
    __shared__ float Wo1s[96 * 64];
    __shared__ float Wo2s[64];
    __shared__ float joins[32][96];
    __shared__ float part[8];

    int tid = threadIdx.x;
    for (int i = tid; i < 96 * 64; i += 256) Wo1s[i] = g_Wo1T[i];
    if (tid < 64) Wo2s[tid] = Wo2[tid];

    int base = blockIdx.x * 32;
    for (int i = tid; i < 32 * 96; i += 256) {
        int rr = i / 96;
        int k = i - rr * 96;
        int bn = base + rr;
        joins[rr][k] = (k < 64) ? g_s2[(long)bn * 64 + k] : ann[(long)bn * 32 + (k - 64)];
    }
    __syncthreads();

    int q = tid >> 6;
    int d = tid & 63;
    for (int rr = 0; rr < 32; rr += 4) {
        int r = rr + q;
        float acc = 0.f;
#pragma unroll
        for (int k = 0; k < 96; k++) acc += joins[r][k] * Wo1s[k * 64 + d];
        float v = tanhf(acc) * Wo2s[d];
#pragma unroll
        for (int off = 16; off > 0; off >>= 1)
            v += __shfl_down_sync(0xffffffffu, v, off);
        int w = tid >> 5;
        if ((tid & 31) == 0) part[w] = v;
        __syncthreads();
        if (tid < 4) out[base + rr + tid] = part[2 * tid] + part[2 * tid + 1];
        __syncthreads();
    }
}

// ---------------- launch ----------------
extern "C" void kernel_launch(void* const* d_in, const int* in_sizes, int n_in,
                              void* d_out, int out_size) {
    const float* prop  = (const float*)d_in[0];
    const float* ann   = (const float*)d_in[1];
    const float* A     = (const float*)d_in[2];
    const float* W_in  = (const float*)d_in[3];
    const float* W_out = (const float*)d_in[4];
    const float* W_r   = (const float*)d_in[5];
    const float* W_z   = (const float*)d_in[6];
    const float* W_h   = (const float*)d_in[7];
    const float* Wo1   = (const float*)d_in[8];
    const float* Wo2   = (const float*)d_in[9];
    float* out = (float*)d_out;

    const int EW_BLOCKS = (BNT * 64 + 255) / 256;

    static bool attr_set = false;
    if (!attr_set) {
        cudaFuncSetAttribute(k_big_mma, cudaFuncAttributeMaxDynamicSharedMemorySize, SMEM_DYN);
        attr_set = true;
    }

    k_pack_weights<<<(75776 + 255) / 256, 256>>>(W_in, W_out, W_r, W_z, W_h, Wo1);

    // ---- propagate step 1 ----
    k_pack_state<<<EW_BLOCKS, 256>>>(prop, 0);
    k_sproj<<<dim3(16, 1, 64), 256>>>(prop, 0);
    k_big_mma<<<dim3(8, 16, 1), 256, SMEM_DYN>>>(A);
    k_rz<<<dim3(125, 2, 1), 256>>>();
    k_gates_r<<<EW_BLOCKS, 256>>>(prop, 0);
    k_h<<<dim3(125, 1, 1), 256>>>();
    k_update<<<EW_BLOCKS, 256>>>(prop, 0, 1);

    // ---- propagate step 2 ----
    k_pack_state<<<EW_BLOCKS, 256>>>(prop, 1);
    k_sproj<<<dim3(16, 1, 64), 256>>>(prop, 1);
    k_big_mma<<<dim3(8, 16, 1), 256, SMEM_DYN>>>(A);
    k_rz<<<dim3(125, 2, 1), 256>>>();
    k_gates_r<<<EW_BLOCKS, 256>>>(prop, 1);
    k_h<<<dim3(125, 1, 1), 256>>>();
    k_update<<<EW_BLOCKS, 256>>>(prop, 1, 2);

    // ---- output head ----
    k_out<<<250, 256>>>(ann, Wo2, out);
}